// round 4
// baseline (speedup 1.0000x reference)
#include <cuda_runtime.h>
#include <math.h>

#define GDIM 128
#define G3 (GDIM*GDIM*GDIM)
#define NPART 4096
#define NKEY 512           // 64 c0-bins (width 2) x 8 c1-subbins (width 16)

// Sorted particle data (scratch; __device__ globals, no allocation)
__device__ float4 g_ps[NPART * 2];     // [2p]=(gp0,gp1,gp2,omega) [2p+1]=(em0..3)
__device__ int    g_pcs[NPART + 32];   // packed floor cell, +32 pad sentinels
__device__ int    g_bs2[NKEY + 1];     // key -> start offset

// ---------------------------------------------------------------------------
// Fused prep + deterministic stable counting sort by key=(c0>>1)*8 | (c1>>4).
// Single block, 1024 threads = 32 warps; warp w owns particles [128w,128w+128)
// in 4 chunks of 32; per-warp running counters give stable local rank.
// ---------------------------------------------------------------------------
__global__ void __launch_bounds__(1024)
sort_kernel(const float* __restrict__ pos,
            const float* __restrict__ inten,
            const float* __restrict__ emo) {
    __shared__ unsigned short cnt[32][NKEY];   // per-warp key counts -> prefixes
    __shared__ int bstart[NKEY + 1];
    __shared__ int wtot[16];
    const int tid  = threadIdx.x;
    const int w    = tid >> 5;
    const int lane = tid & 31;
    const unsigned FULL = 0xffffffffu;
    const unsigned lmlt = (1u << lane) - 1u;

    for (int i = tid; i < 32 * NKEY / 2; i += 1024) ((int*)cnt)[i] = 0;
    __syncthreads();

    int    mypc[4], mykey[4], myrank[4];
    float4 mypA[4], mypE[4];
#pragma unroll
    for (int k = 0; k < 4; k++) {
        const int i = w * 128 + k * 32 + lane;
        const float gp0 = (pos[3*i+0] + 1.0f) * 63.5f;
        const float gp1 = (pos[3*i+1] + 1.0f) * 63.5f;
        const float gp2 = (pos[3*i+2] + 1.0f) * 63.5f;
        const int c0 = min(max((int)floorf(gp0), 0), GDIM-1);
        const int c1 = min(max((int)floorf(gp1), 0), GDIM-1);
        const int c2 = min(max((int)floorf(gp2), 0), GDIM-1);
        mypc[k] = c0 | (c1 << 8) | (c2 << 16);
        const int key = ((c0 >> 1) << 3) | (c1 >> 4);
        const unsigned m = __match_any_sync(FULL, key);
        const int r = __popc(m & lmlt);
        mykey[k]  = key;
        myrank[k] = (int)cnt[w][key] + r;     // running count + rank in chunk
        __syncwarp();
        if (r == 0) cnt[w][key] = (unsigned short)(cnt[w][key] + __popc(m));
        __syncwarp();
        mypA[k] = make_float4(gp0, gp1, gp2, inten[i] * 0.01f);
        mypE[k] = make_float4(emo[4*i+0], emo[4*i+1], emo[4*i+2], emo[4*i+3]);
    }
    __syncthreads();

    // Exclusive prefix over the 32 warps for each key (thread t owns key t).
    if (tid < NKEY) {
        int s = 0;
#pragma unroll
        for (int wi = 0; wi < 32; wi++) {
            const int v = cnt[wi][tid]; cnt[wi][tid] = (unsigned short)s; s += v;
        }
        bstart[tid] = s;   // key totals (temporarily)
    }
    __syncthreads();

    // Exclusive scan of the 512 key totals: 16 warp-chunks + carry pass.
    int vin = 0, v0 = 0, b = 0;
    if (w < 16) {
        b = w * 32 + lane;
        v0 = bstart[b];
        vin = v0;
#pragma unroll
        for (int d = 1; d < 32; d <<= 1) {
            const int t = __shfl_up_sync(FULL, vin, d);
            if (lane >= d) vin += t;
        }
        if (lane == 31) wtot[w] = vin;
    }
    __syncthreads();
    if (tid == 0) {
        int s = 0;
#pragma unroll
        for (int i = 0; i < 16; i++) { const int t = wtot[i]; wtot[i] = s; s += t; }
    }
    __syncthreads();
    if (w < 16) bstart[b] = wtot[w] + vin - v0;    // global exclusive prefix
    if (tid == 0) bstart[NKEY] = NPART;
    __syncthreads();

#pragma unroll
    for (int k = 0; k < 4; k++) {
        const int p = bstart[mykey[k]] + (int)cnt[w][mykey[k]] + myrank[k];
        g_pcs[p]      = mypc[k];
        g_ps[2*p + 0] = mypA[k];
        g_ps[2*p + 1] = mypE[k];
    }
    if (tid <= NKEY) g_bs2[tid] = bstart[tid];
    if (tid < 32)    g_pcs[NPART + tid] = 0x0000FF00;   // c1=255: fails windows
}

// ---------------------------------------------------------------------------
// One warp per sample. Each lane owns ONE of the 32 cells actually needed:
// 8 trilinear corners (block coords in {1,2}^3) + their 24 face neighbors.
// Scan iterates the <=12 row segments of the 2-level binned order.
// ---------------------------------------------------------------------------
__global__ void __launch_bounds__(128)
main_kernel(const float* __restrict__ spos,
            const float* __restrict__ H0,
            const float* __restrict__ E0,
            float* __restrict__ out) {
    __shared__ float sv[4][5][64];
    const unsigned FULL = 0xffffffffu;
    const int wib  = threadIdx.x >> 5;
    const int lane = threadIdx.x & 31;
    const int s    = (blockIdx.x << 2) + wib;

    const float px = spos[3*s+0];
    const float py = spos[3*s+1];
    const float pz = spos[3*s+2];
    // grid axis0 <- comp2, axis1 <- comp1, axis2 <- comp0 (reference transpose)
    const float t0 = fminf(fmaxf((pz + 1.0f) * 63.5f, 0.0f), 127.0f);
    const float t1 = fminf(fmaxf((py + 1.0f) * 63.5f, 0.0f), 127.0f);
    const float t2 = fminf(fmaxf((px + 1.0f) * 63.5f, 0.0f), 127.0f);
    const int i0 = (int)floorf(t0); const float f0 = t0 - (float)i0;
    const int i1 = (int)floorf(t1); const float f1 = t1 - (float)i1;
    const int i2 = (int)floorf(t2); const float f2 = t2 - (float)i2;

    // lane -> block coords (b0,b1,b2), covering the 32 needed cells
    int b0, b1, b2;
    if (lane < 8) {
        b0 = 1 + ((lane >> 2) & 1); b1 = 1 + ((lane >> 1) & 1); b2 = 1 + (lane & 1);
    } else {
        const int idx = lane - 8, axis = idx >> 3, rest = idx & 7;
        const int s3 = ((rest >> 2) & 1) * 3;
        const int u = 1 + ((rest >> 1) & 1), v = 1 + (rest & 1);
        b0 = (axis == 0) ? s3 : u;
        b1 = (axis == 1) ? s3 : ((axis == 0) ? u : v);
        b2 = (axis == 2) ? s3 : v;
    }
    const int gc0 = min(max(i0 - 1 + b0, 0), 127);
    const int gc1 = min(max(i1 - 1 + b1, 0), 127);
    const int gc2 = min(max(i2 - 1 + b2, 0), 127);
    const float gcf0 = (float)gc0, gcf1 = (float)gc1, gcf2 = (float)gc2;
    const unsigned gcpack = (unsigned)(gc0 | (gc1 << 8) | (gc2 << 16));

    // particle-window (covers all 32 cells)
    const int lo0 = min(max(i0 - 1, 0), 127) - 9, hi0 = min(max(i0 + 2, 0), 127) + 9;
    const int lo1 = min(max(i1 - 1, 0), 127) - 9, hi1 = min(max(i1 + 2, 0), 127) + 9;
    const int lo2 = min(max(i2 - 1, 0), 127) - 9, hi2 = min(max(i2 + 2, 0), 127) + 9;
    const unsigned sp0 = (unsigned)(hi0 - lo0);
    const unsigned sp1 = (unsigned)(hi1 - lo1);
    const unsigned sp2 = (unsigned)(hi2 - lo2);

    const int r0  = max(lo0, 0) >> 1;
    const int r1  = min(hi0, 127) >> 1;
    const int slo = max(lo1, 0) >> 4;
    const int shi = min(hi1, 127) >> 4;

    float aH = 0.f, aE0 = 0.f, aE1 = 0.f, aE2 = 0.f, aE3 = 0.f;

    for (int r = r0; r <= r1; r++) {
        const int rb = r << 3;
        const int j0 = g_bs2[rb + slo];
        const int j1 = g_bs2[rb + shi + 1];
        for (int base = j0 & ~31; base < j1; base += 32) {
            const int idx = base + lane;
            const int pcv = g_pcs[idx];
            const int c0 = pcv & 255, c1 = (pcv >> 8) & 255, c2 = (pcv >> 16) & 255;
            const bool hit = ((unsigned)(c0 - lo0) <= sp0) &
                             ((unsigned)(c1 - lo1) <= sp1) &
                             ((unsigned)(c2 - lo2) <= sp2) &
                             (idx >= j0) & (idx < j1);
            unsigned msk = __ballot_sync(FULL, hit);
            while (msk) {
                const int j = __ffs(msk) - 1;
                msk &= msk - 1;
                const int pcj = __shfl_sync(FULL, pcv, j);
                const float4 A  = __ldg(&g_ps[2*(base + j) + 0]);
                const float4 Em = __ldg(&g_ps[2*(base + j) + 1]);
                const unsigned diff = __vabsdiffu4((unsigned)pcj, gcpack);
                const bool in = (__vcmpleu4(diff, 0x09090909u) == 0xFFFFFFFFu);
                const float d0 = gcf0 - A.x;
                const float d1 = gcf1 - A.y;
                const float d2 = gcf2 - A.z;
                const float ssum = fmaf(d0, d0, fmaf(d1, d1, d2 * d2));
                const float e = __expf(ssum * -0.048828125f);
                float wv = in ? A.w : 0.0f;
                wv *= e;
                aH  += wv;
                aE0 += wv * Em.x;  aE1 += wv * Em.y;
                aE2 += wv * Em.z;  aE3 += wv * Em.w;
            }
        }
    }

    // add base grid values, stash in shared (only the 32 needed slots)
    const int ci   = b0 * 16 + b1 * 4 + b2;
    const int flat = (gc0 * GDIM + gc1) * GDIM + gc2;
    sv[wib][0][ci] = aH  + __ldg(&H0[flat]);
    sv[wib][1][ci] = aE0 + __ldg(&E0[0*G3 + flat]);
    sv[wib][2][ci] = aE1 + __ldg(&E0[1*G3 + flat]);
    sv[wib][3][ci] = aE2 + __ldg(&E0[2*G3 + flat]);
    sv[wib][4][ci] = aE3 + __ldg(&E0[3*G3 + flat]);
    __syncwarp();

    // diffusion step + ReLU + trilinear reduce (8 corner lanes)
#pragma unroll
    for (int ch = 0; ch < 5; ch++) {
        float part = 0.0f;
        if (lane < 8) {
            const int d0 = (lane >> 2) & 1, d1c = (lane >> 1) & 1, d2c = lane & 1;
            const int cc = (1 + d0) * 16 + (1 + d1c) * 4 + (1 + d2c);
            const float* v = sv[wib][ch];
            const float c = v[cc];
            const float lap = v[cc-16] + v[cc+16] + v[cc-4] + v[cc+4]
                            + v[cc-1]  + v[cc+1]  - 6.0f * c;
            float val;
            if (ch == 0) val = c * (1.0f - 5e-5f) + 0.002f * lap;
            else         val = c * (1.0f - 5e-5f) + 5e-5f + 0.001f * lap;
            val = fmaxf(val, 0.0f);
            const float wq = (d0  ? f0 : 1.0f - f0)
                           * (d1c ? f1 : 1.0f - f1)
                           * (d2c ? f2 : 1.0f - f2);
            part = val * wq;
        }
        part += __shfl_down_sync(FULL, part, 4);
        part += __shfl_down_sync(FULL, part, 2);
        part += __shfl_down_sync(FULL, part, 1);
        if (lane == 0) out[s * 5 + ch] = part;
    }
}

extern "C" void kernel_launch(void* const* d_in, const int* in_sizes, int n_in,
                              void* d_out, int out_size) {
    const float* positions   = (const float*)d_in[0];  // (4096,3)
    const float* intensities = (const float*)d_in[1];  // (4096,)
    const float* emotions    = (const float*)d_in[2];  // (4096,4)
    const float* sample_pos  = (const float*)d_in[3];  // (8,1024,3)
    const float* H0          = (const float*)d_in[4];  // (128,128,128)
    const float* E0          = (const float*)d_in[5];  // (4,128,128,128)
    float* out = (float*)d_out;                        // (8,1024,5)

    sort_kernel<<<1, 1024>>>(positions, intensities, emotions);
    main_kernel<<<2048, 128>>>(sample_pos, H0, E0, out);
    (void)in_sizes; (void)n_in; (void)out_size;
}

// round 5
// speedup vs baseline: 1.2356x; 1.2356x over previous
#include <cuda_runtime.h>
#include <math.h>

#define GDIM 128
#define G3 (GDIM*GDIM*GDIM)
#define NPART 4096
#define NKEY 512           // 64 c0-bins (width 2) x 8 c1-subbins (width 16)
#define NBLK 32            // sort blocks (128 particles each)

// Scratch (__device__ globals, no allocation)
__device__ float4 g_ps[NPART * 2];      // [2p]=(gp0,gp1,gp2,omega) [2p+1]=(em0..3)
__device__ int    g_pcs[NPART + 32];    // packed floor cell, +32 pad sentinels
__device__ int    g_bs2[NKEY + 1];      // key -> global start offset
__device__ int    g_hist[NBLK * NKEY];  // per-block key histograms
__device__ int    g_boff[NBLK * NKEY];  // per-block per-key exclusive offsets

__device__ __forceinline__ int particle_key(const float* pos, int i,
                                            int& pc, float& gp0, float& gp1, float& gp2) {
    gp0 = (pos[3*i+0] + 1.0f) * 63.5f;
    gp1 = (pos[3*i+1] + 1.0f) * 63.5f;
    gp2 = (pos[3*i+2] + 1.0f) * 63.5f;
    const int c0 = min(max((int)floorf(gp0), 0), GDIM-1);
    const int c1 = min(max((int)floorf(gp1), 0), GDIM-1);
    const int c2 = min(max((int)floorf(gp2), 0), GDIM-1);
    pc = c0 | (c1 << 8) | (c2 << 16);
    return ((c0 >> 1) << 3) | (c1 >> 4);
}

// ---------------------------------------------------------------------------
// Sort stage 1: per-block key histograms (32 blocks x 128 particles).
// ---------------------------------------------------------------------------
__global__ void __launch_bounds__(128)
hist_kernel(const float* __restrict__ pos) {
    __shared__ int h[NKEY];
    const int tid = threadIdx.x;
#pragma unroll
    for (int k = 0; k < NKEY / 128; k++) h[tid + k * 128] = 0;
    __syncthreads();
    int pc; float a, b, c;
    const int key = particle_key(pos, blockIdx.x * 128 + tid, pc, a, b, c);
    atomicAdd(&h[key], 1);
    __syncthreads();
#pragma unroll
    for (int k = 0; k < NKEY / 128; k++) {
        const int t = tid + k * 128;
        g_hist[blockIdx.x * NKEY + t] = h[t];
    }
}

// ---------------------------------------------------------------------------
// Sort stage 2: per-key prefix across blocks + global 512-key exclusive scan.
// One block, 512 threads; thread t owns key t.
// ---------------------------------------------------------------------------
__global__ void __launch_bounds__(512)
offsets_kernel() {
    __shared__ int tot[NKEY];
    __shared__ int wtot[16];
    const int t    = threadIdx.x;
    const int w    = t >> 5;
    const int lane = t & 31;
    const unsigned FULL = 0xffffffffu;

    int s = 0;
#pragma unroll
    for (int b = 0; b < NBLK; b++) {
        const int v = g_hist[b * NKEY + t];
        g_boff[b * NKEY + t] = s;
        s += v;
    }
    tot[t] = s;
    __syncthreads();

    int vin = tot[t];
    const int v0 = vin;
#pragma unroll
    for (int d = 1; d < 32; d <<= 1) {
        const int u = __shfl_up_sync(FULL, vin, d);
        if (lane >= d) vin += u;
    }
    if (lane == 31) wtot[w] = vin;
    __syncthreads();
    if (t == 0) {
        int c = 0;
#pragma unroll
        for (int i = 0; i < 16; i++) { const int x = wtot[i]; wtot[i] = c; c += x; }
    }
    __syncthreads();
    g_bs2[t] = wtot[w] + vin - v0;   // global exclusive prefix
    if (t == 0) g_bs2[NKEY] = NPART;
}

// ---------------------------------------------------------------------------
// Sort stage 3: stable scatter (32 blocks x 128 threads = 4 warps).
// rank = g_bs2[key] + g_boff[blk][key] + (4-warp smem prefix) + in-warp rank.
// ---------------------------------------------------------------------------
__global__ void __launch_bounds__(128)
scatter_kernel(const float* __restrict__ pos,
               const float* __restrict__ inten,
               const float* __restrict__ emo) {
    __shared__ int wcnt[4][NKEY];
    const int tid  = threadIdx.x;
    const int w    = tid >> 5;
    const int lane = tid & 31;
    const unsigned FULL = 0xffffffffu;

#pragma unroll
    for (int k = 0; k < 4 * NKEY / 128; k++) ((int*)wcnt)[tid + k * 128] = 0;
    __syncthreads();

    const int i = blockIdx.x * 128 + tid;
    int pc; float gp0, gp1, gp2;
    const int key = particle_key(pos, i, pc, gp0, gp1, gp2);
    const unsigned m = __match_any_sync(FULL, key);
    const int r = __popc(m & ((1u << lane) - 1u));
    if (r == 0) wcnt[w][key] = __popc(m);
    __syncthreads();

    // exclusive prefix across the 4 warps, per key (128 threads x 4 keys each)
#pragma unroll
    for (int k = 0; k < NKEY / 128; k++) {
        const int t = tid + k * 128;
        int s = 0;
#pragma unroll
        for (int wi = 0; wi < 4; wi++) { const int v = wcnt[wi][t]; wcnt[wi][t] = s; s += v; }
    }
    __syncthreads();

    const int p = g_bs2[key] + g_boff[blockIdx.x * NKEY + key] + wcnt[w][key] + r;
    g_pcs[p]      = pc;
    g_ps[2*p + 0] = make_float4(gp0, gp1, gp2, inten[i] * 0.01f);
    g_ps[2*p + 1] = make_float4(emo[4*i+0], emo[4*i+1], emo[4*i+2], emo[4*i+3]);

    if (blockIdx.x == 0 && tid < 32) g_pcs[NPART + tid] = 0x0000FF00; // sentinel
}

// ---------------------------------------------------------------------------
// One warp per sample. Each lane owns ONE of the 32 cells actually needed:
// 8 trilinear corners (block coords in {1,2}^3) + their 24 face neighbors.
// Scan iterates the <=12 row segments of the 2-level binned order.
// ---------------------------------------------------------------------------
__global__ void __launch_bounds__(64)
main_kernel(const float* __restrict__ spos,
            const float* __restrict__ H0,
            const float* __restrict__ E0,
            float* __restrict__ out) {
    __shared__ float sv[2][5][64];
    const unsigned FULL = 0xffffffffu;
    const int wib  = threadIdx.x >> 5;
    const int lane = threadIdx.x & 31;
    const int s    = (blockIdx.x << 1) + wib;

    const float px = spos[3*s+0];
    const float py = spos[3*s+1];
    const float pz = spos[3*s+2];
    // grid axis0 <- comp2, axis1 <- comp1, axis2 <- comp0 (reference transpose)
    const float t0 = fminf(fmaxf((pz + 1.0f) * 63.5f, 0.0f), 127.0f);
    const float t1 = fminf(fmaxf((py + 1.0f) * 63.5f, 0.0f), 127.0f);
    const float t2 = fminf(fmaxf((px + 1.0f) * 63.5f, 0.0f), 127.0f);
    const int i0 = (int)floorf(t0); const float f0 = t0 - (float)i0;
    const int i1 = (int)floorf(t1); const float f1 = t1 - (float)i1;
    const int i2 = (int)floorf(t2); const float f2 = t2 - (float)i2;

    // lane -> block coords (b0,b1,b2), covering the 32 needed cells
    int b0, b1, b2;
    if (lane < 8) {
        b0 = 1 + ((lane >> 2) & 1); b1 = 1 + ((lane >> 1) & 1); b2 = 1 + (lane & 1);
    } else {
        const int idx = lane - 8, axis = idx >> 3, rest = idx & 7;
        const int s3 = ((rest >> 2) & 1) * 3;
        const int u = 1 + ((rest >> 1) & 1), v = 1 + (rest & 1);
        b0 = (axis == 0) ? s3 : u;
        b1 = (axis == 1) ? s3 : ((axis == 0) ? u : v);
        b2 = (axis == 2) ? s3 : v;
    }
    const int gc0 = min(max(i0 - 1 + b0, 0), 127);
    const int gc1 = min(max(i1 - 1 + b1, 0), 127);
    const int gc2 = min(max(i2 - 1 + b2, 0), 127);
    const float gcf0 = (float)gc0, gcf1 = (float)gc1, gcf2 = (float)gc2;
    const unsigned gcpack = (unsigned)(gc0 | (gc1 << 8) | (gc2 << 16));

    // particle-window (covers all 32 cells)
    const int lo0 = min(max(i0 - 1, 0), 127) - 9, hi0 = min(max(i0 + 2, 0), 127) + 9;
    const int lo1 = min(max(i1 - 1, 0), 127) - 9, hi1 = min(max(i1 + 2, 0), 127) + 9;
    const int lo2 = min(max(i2 - 1, 0), 127) - 9, hi2 = min(max(i2 + 2, 0), 127) + 9;
    const unsigned sp0 = (unsigned)(hi0 - lo0);
    const unsigned sp1 = (unsigned)(hi1 - lo1);
    const unsigned sp2 = (unsigned)(hi2 - lo2);

    const int r0  = max(lo0, 0) >> 1;
    const int r1  = min(hi0, 127) >> 1;
    const int slo = max(lo1, 0) >> 4;
    const int shi = min(hi1, 127) >> 4;

    float aH = 0.f, aE0 = 0.f, aE1 = 0.f, aE2 = 0.f, aE3 = 0.f;

    for (int r = r0; r <= r1; r++) {
        const int rb = r << 3;
        const int j0 = g_bs2[rb + slo];
        const int j1 = g_bs2[rb + shi + 1];
        for (int base = j0 & ~31; base < j1; base += 32) {
            const int idx = base + lane;
            const int pcv = g_pcs[idx];
            const int c0 = pcv & 255, c1 = (pcv >> 8) & 255, c2 = (pcv >> 16) & 255;
            const bool hit = ((unsigned)(c0 - lo0) <= sp0) &
                             ((unsigned)(c1 - lo1) <= sp1) &
                             ((unsigned)(c2 - lo2) <= sp2) &
                             (idx >= j0) & (idx < j1);
            unsigned msk = __ballot_sync(FULL, hit);
            while (msk) {
                const int j = __ffs(msk) - 1;
                msk &= msk - 1;
                const int pcj = __shfl_sync(FULL, pcv, j);
                const float4 A  = __ldg(&g_ps[2*(base + j) + 0]);
                const float4 Em = __ldg(&g_ps[2*(base + j) + 1]);
                const unsigned diff = __vabsdiffu4((unsigned)pcj, gcpack);
                const bool in = (__vcmpleu4(diff, 0x09090909u) == 0xFFFFFFFFu);
                const float d0 = gcf0 - A.x;
                const float d1 = gcf1 - A.y;
                const float d2 = gcf2 - A.z;
                const float ssum = fmaf(d0, d0, fmaf(d1, d1, d2 * d2));
                const float e = __expf(ssum * -0.048828125f);
                float wv = in ? A.w : 0.0f;
                wv *= e;
                aH  += wv;
                aE0 += wv * Em.x;  aE1 += wv * Em.y;
                aE2 += wv * Em.z;  aE3 += wv * Em.w;
            }
        }
    }

    // add base grid values, stash in shared (only the 32 needed slots)
    const int ci   = b0 * 16 + b1 * 4 + b2;
    const int flat = (gc0 * GDIM + gc1) * GDIM + gc2;
    sv[wib][0][ci] = aH  + __ldg(&H0[flat]);
    sv[wib][1][ci] = aE0 + __ldg(&E0[0*G3 + flat]);
    sv[wib][2][ci] = aE1 + __ldg(&E0[1*G3 + flat]);
    sv[wib][3][ci] = aE2 + __ldg(&E0[2*G3 + flat]);
    sv[wib][4][ci] = aE3 + __ldg(&E0[3*G3 + flat]);
    __syncwarp();

    // diffusion step + ReLU + trilinear reduce (8 corner lanes)
#pragma unroll
    for (int ch = 0; ch < 5; ch++) {
        float part = 0.0f;
        if (lane < 8) {
            const int d0 = (lane >> 2) & 1, d1c = (lane >> 1) & 1, d2c = lane & 1;
            const int cc = (1 + d0) * 16 + (1 + d1c) * 4 + (1 + d2c);
            const float* v = sv[wib][ch];
            const float c = v[cc];
            const float lap = v[cc-16] + v[cc+16] + v[cc-4] + v[cc+4]
                            + v[cc-1]  + v[cc+1]  - 6.0f * c;
            float val;
            if (ch == 0) val = c * (1.0f - 5e-5f) + 0.002f * lap;
            else         val = c * (1.0f - 5e-5f) + 5e-5f + 0.001f * lap;
            val = fmaxf(val, 0.0f);
            const float wq = (d0  ? f0 : 1.0f - f0)
                           * (d1c ? f1 : 1.0f - f1)
                           * (d2c ? f2 : 1.0f - f2);
            part = val * wq;
        }
        part += __shfl_down_sync(FULL, part, 4);
        part += __shfl_down_sync(FULL, part, 2);
        part += __shfl_down_sync(FULL, part, 1);
        if (lane == 0) out[s * 5 + ch] = part;
    }
}

extern "C" void kernel_launch(void* const* d_in, const int* in_sizes, int n_in,
                              void* d_out, int out_size) {
    const float* positions   = (const float*)d_in[0];  // (4096,3)
    const float* intensities = (const float*)d_in[1];  // (4096,)
    const float* emotions    = (const float*)d_in[2];  // (4096,4)
    const float* sample_pos  = (const float*)d_in[3];  // (8,1024,3)
    const float* H0          = (const float*)d_in[4];  // (128,128,128)
    const float* E0          = (const float*)d_in[5];  // (4,128,128,128)
    float* out = (float*)d_out;                        // (8,1024,5)

    hist_kernel<<<NBLK, 128>>>(positions);
    offsets_kernel<<<1, 512>>>();
    scatter_kernel<<<NBLK, 128>>>(positions, intensities, emotions);
    main_kernel<<<4096, 64>>>(sample_pos, H0, E0, out);
    (void)in_sizes; (void)n_in; (void)out_size;
}